// round 5
// baseline (speedup 1.0000x reference)
#include <cuda_runtime.h>
#include <cstdint>

#define NN 4096
#define EE 8192
#define FDIM 64
#define BN_EPS 1e-5f
#define TRIP_CAP 131072
#define TOTROWS (NN + EE + NN)     // pd rows, lg rows, pm rows
#define NBLK 740
#define CHUNK 8192                 // bytes per bulk copy (2048 floats)
#define NSTAGE 4

// ---------------- device scratch ----------------
__device__ float g_pd_y[NN * FDIM];
__device__ float g_x[NN * FDIM];
__device__ float g_lg_y[EE * FDIM];
__device__ float g_pm_x[EE * FDIM];
__device__ float g_stats[256];
__device__ int   g_cnt;
__device__ int   g_trip_n[TRIP_CAP];
__device__ int   g_trip_e[TRIP_CAP];
__device__ float g_trip_v[TRIP_CAP];

// ---------------- init ----------------
__global__ __launch_bounds__(256) void k_init() {
    int idx = blockIdx.x * 256 + threadIdx.x;              // 512*256 = 131072
    reinterpret_cast<float4*>(g_pm_x)[idx] = make_float4(0.f, 0.f, 0.f, 0.f);
    if (idx < 256) g_stats[idx] = 0.f;
    if (idx == 0) g_cnt = 0;
}

// ---------------- helpers ----------------
__device__ __forceinline__ unsigned nz4(float4 v) {
    return __float_as_uint(v.x) | __float_as_uint(v.y) |
           __float_as_uint(v.z) | __float_as_uint(v.w);
}

__device__ __forceinline__ void gath_chunk(float4 v, unsigned ored, int colbase, int lane,
                                           const float* __restrict__ B,
                                           float& acc0, float& acc1) {
    unsigned mask = __ballot_sync(0xffffffffu, ored != 0u);
    while (mask) {
        int src = __ffs(mask) - 1;
        mask &= mask - 1;
        float b0 = __shfl_sync(0xffffffffu, v.x, src);
        float b1 = __shfl_sync(0xffffffffu, v.y, src);
        float b2 = __shfl_sync(0xffffffffu, v.z, src);
        float b3 = __shfl_sync(0xffffffffu, v.w, src);
        const float* bp = B + (size_t)(colbase + (src << 2)) * FDIM + lane;
        if (b0 != 0.f) { acc0 = fmaf(b0, bp[0],   acc0); acc1 = fmaf(b0, bp[32],  acc1); }
        if (b1 != 0.f) { acc0 = fmaf(b1, bp[64],  acc0); acc1 = fmaf(b1, bp[96],  acc1); }
        if (b2 != 0.f) { acc0 = fmaf(b2, bp[128], acc0); acc1 = fmaf(b2, bp[160], acc1); }
        if (b3 != 0.f) { acc0 = fmaf(b3, bp[192], acc0); acc1 = fmaf(b3, bp[224], acc1); }
    }
}

__device__ __forceinline__ void pm_emit(float4 v, int col0, int n) {
    int k = (v.x != 0.f) + (v.y != 0.f) + (v.z != 0.f) + (v.w != 0.f);
    if (!k) return;
    int pos = atomicAdd(&g_cnt, k);
    float vals[4] = {v.x, v.y, v.z, v.w};
    #pragma unroll
    for (int j = 0; j < 4; ++j) {
        if (vals[j] != 0.f && pos < TRIP_CAP) {
            g_trip_n[pos] = n;
            g_trip_e[pos] = col0 + j;
            g_trip_v[pos] = vals[j];
            ++pos;
        }
    }
}

__device__ __forceinline__ void mbar_wait(uint32_t mbar, int phase) {
    asm volatile(
        "{\n\t"
        ".reg .pred P;\n\t"
        "WAIT_%=:\n\t"
        "mbarrier.try_wait.parity.acquire.cta.shared::cta.b64 P, [%0], %1, 0x989680;\n\t"
        "@P bra.uni DONE_%=;\n\t"
        "bra.uni WAIT_%=;\n\t"
        "DONE_%=:\n\t"
        "}"
        :: "r"(mbar), "r"(phase) : "memory");
}

// ---------------- TMA-fed mega-scan ----------------
// rows: pd [0,4096), lg [4096,12288), pm [12288,16384)
// CTA b processes rows b, b+NBLK, b+2*NBLK, ... Each row = 4 chunks of 8KB
// streamed into a 4-stage SMEM ring via cp.async.bulk.
__global__ void __launch_bounds__(256, 5) k_megascan(const float* __restrict__ pd,
                                                     const float* __restrict__ lg,
                                                     const float* __restrict__ pm,
                                                     const float* __restrict__ y) {
    __shared__ __align__(16) float s_buf[NSTAGE * (CHUNK / 4)];
    __shared__ __align__(8) unsigned long long s_mbar[NSTAGE];
    __shared__ float s_red[8 * 64];

    int t = threadIdx.x;
    int lane = t & 31;
    int w = t >> 5;

    uint32_t buf_base, mbar_base;
    {
        uint32_t a;
        asm("{ .reg .u64 tmp; cvta.to.shared.u64 tmp, %1; cvt.u32.u64 %0, tmp; }"
            : "=r"(a) : "l"((void*)s_buf));
        buf_base = a;
        asm("{ .reg .u64 tmp; cvta.to.shared.u64 tmp, %1; cvt.u32.u64 %0, tmp; }"
            : "=r"(a) : "l"((void*)s_mbar));
        mbar_base = a;
    }

    int nrows = (TOTROWS - blockIdx.x + NBLK - 1) / NBLK;
    int titer = nrows * 4;

    // src address for iteration i
    auto src_of = [&](int i) -> const float* {
        int rl = i >> 2, c = i & 3;
        int rowid = blockIdx.x + rl * NBLK;
        const float* base;
        if (rowid < NN)           base = pd + (size_t)rowid * EE;
        else if (rowid < NN + EE) base = lg + (size_t)(rowid - NN) * EE;
        else                      base = pm + (size_t)(rowid - NN - EE) * EE;
        return base + c * (CHUNK / 4);
    };

    if (t == 0) {
        #pragma unroll
        for (int s = 0; s < NSTAGE; ++s)
            asm volatile("mbarrier.init.shared.b64 [%0], 1;"
                         :: "r"(mbar_base + s * 8) : "memory");
    }
    __syncthreads();

    if (t == 0) {
        int npre = titer < NSTAGE ? titer : NSTAGE;
        for (int k = 0; k < npre; ++k) {
            uint32_t mb = mbar_base + k * 8;
            asm volatile("mbarrier.arrive.expect_tx.shared.b64 _, [%0], %1;"
                         :: "r"(mb), "r"((unsigned)CHUNK) : "memory");
            asm volatile("cp.async.bulk.shared::cluster.global.mbarrier::complete_tx::bytes "
                         "[%0], [%1], %2, [%3];"
                         :: "r"(buf_base + k * CHUNK), "l"(src_of(k)),
                            "r"((unsigned)CHUNK), "r"(mb) : "memory");
        }
    }

    float acc0 = 0.f, acc1 = 0.f;

    for (int i = 0; i < titer; ++i) {
        int s = i & 3;
        int ph = (i >> 2) & 1;
        int rl = i >> 2, c = i & 3;
        int rowid = blockIdx.x + rl * NBLK;
        int mode, row;
        if (rowid < NN)           { mode = 0; row = rowid; }
        else if (rowid < NN + EE) { mode = 1; row = rowid - NN; }
        else                      { mode = 2; row = rowid - NN - EE; }

        mbar_wait(mbar_base + s * 8, ph);

        // scan this warp's 1KB: columns [c*2048 + w*256, +256)
        const float4* seg = reinterpret_cast<const float4*>(
            s_buf + s * (CHUNK / 4) + w * 256);
        float4 v0 = seg[lane];
        float4 v1 = seg[lane + 32];
        unsigned o0 = nz4(v0), o1 = nz4(v1);
        int cb = (c << 11) + (w << 8);
        if (mode < 2) {
            if (__ballot_sync(0xffffffffu, (o0 | o1) != 0u)) {
                gath_chunk(v0, o0, cb,       lane, y, acc0, acc1);
                gath_chunk(v1, o1, cb + 128, lane, y, acc0, acc1);
            }
            if (c == 3) {
                s_red[(w << 6) + lane]      = acc0;
                s_red[(w << 6) + lane + 32] = acc1;
                acc0 = 0.f; acc1 = 0.f;
            }
        } else {
            if (__ballot_sync(0xffffffffu, (o0 | o1) != 0u)) {
                int lb = lane << 2;
                if (o0) pm_emit(v0, cb + lb,       row);
                if (o1) pm_emit(v1, cb + 128 + lb, row);
            }
        }

        __syncthreads();   // all warps done with stage s (and s_red complete)

        if (mode < 2 && c == 3 && t < 64) {
            float sum = s_red[t]         + s_red[64 + t]  + s_red[128 + t] + s_red[192 + t]
                      + s_red[256 + t]   + s_red[320 + t] + s_red[384 + t] + s_red[448 + t];
            float* out = (mode == 0 ? g_pd_y : g_lg_y);
            out[(size_t)row * FDIM + t] = sum;
        }

        if (t == 0 && i + NSTAGE < titer) {
            uint32_t mb = mbar_base + s * 8;
            asm volatile("mbarrier.arrive.expect_tx.shared.b64 _, [%0], %1;"
                         :: "r"(mb), "r"((unsigned)CHUNK) : "memory");
            asm volatile("cp.async.bulk.shared::cluster.global.mbarrier::complete_tx::bytes "
                         "[%0], [%1], %2, [%3];"
                         :: "r"(buf_base + s * CHUNK), "l"(src_of(i + NSTAGE)),
                            "r"((unsigned)CHUNK), "r"(mb) : "memory");
        }
    }
}

// ---------------- x linear + concat/relu + BN-x stats ----------------
__global__ __launch_bounds__(256) void k_x_linear(const float* __restrict__ tw,
                                                  const float* __restrict__ tb,
                                                  const float* __restrict__ trw,
                                                  const float* __restrict__ trb) {
    __shared__ float s_in[16 * 64];
    __shared__ float red[256], red2[256];
    int t = threadIdx.x;
    int rowbase = blockIdx.x * 16;
    reinterpret_cast<float4*>(s_in)[t] =
        reinterpret_cast<const float4*>(g_pd_y + (size_t)rowbase * 64)[t];
    __syncthreads();
    int c = t & 63, slot = t >> 6;
    const float* w; float bias; bool dorelu;
    if (c < 32) { w = tw + c * 64;         bias = tb[c];        dorelu = false; }
    else        { w = trw + (c - 32) * 64; bias = trb[c - 32];  dorelu = true;  }
    float acc[4] = {bias, bias, bias, bias};
    #pragma unroll
    for (int f = 0; f < 64; f += 4) {
        float4 wv = *reinterpret_cast<const float4*>(w + f);
        #pragma unroll
        for (int j = 0; j < 4; ++j) {
            float4 pv = *reinterpret_cast<const float4*>(&s_in[(slot + 4 * j) * 64 + f]);
            acc[j] = fmaf(wv.x, pv.x, fmaf(wv.y, pv.y, fmaf(wv.z, pv.z, fmaf(wv.w, pv.w, acc[j]))));
        }
    }
    float s = 0.f, sq = 0.f;
    #pragma unroll
    for (int j = 0; j < 4; ++j) {
        float v = acc[j];
        if (dorelu) v = fmaxf(v, 0.f);
        g_x[(size_t)(rowbase + slot + 4 * j) * 64 + c] = v;
        s += v; sq += v * v;
    }
    red[t] = s; red2[t] = sq;
    __syncthreads();
    if (slot == 0) {
        atomicAdd(&g_stats[c],      red[c] + red[64 + c] + red[128 + c] + red[192 + c]);
        atomicAdd(&g_stats[64 + c], red2[c] + red2[64 + c] + red2[128 + c] + red2[192 + c]);
    }
}

// ---------------- pm triplet apply, fused x-BN: one triplet per warp ----------------
__global__ __launch_bounds__(256) void k_pm_apply(const float* __restrict__ bxw,
                                                  const float* __restrict__ bxb) {
    int lane = threadIdx.x & 31;
    int warp = (blockIdx.x * 256 + threadIdx.x) >> 5;   // 16384 warps

    int cnt = g_cnt;
    if (cnt > TRIP_CAP) cnt = TRIP_CAP;
    if (warp >= cnt) return;

    const float invn = 1.f / NN;
    float m0 = g_stats[lane] * invn;
    float m1 = g_stats[lane + 32] * invn;
    float v0 = g_stats[64 + lane] * invn - m0 * m0;
    float v1 = g_stats[64 + lane + 32] * invn - m1 * m1;
    float sc0 = bxw[lane] * rsqrtf(v0 + BN_EPS);
    float sc1 = bxw[lane + 32] * rsqrtf(v1 + BN_EPS);
    float sh0 = bxb[lane] - m0 * sc0;
    float sh1 = bxb[lane + 32] - m1 * sc1;

    for (int i = warp; i < cnt; i += 16384) {
        int n = g_trip_n[i];
        int e = g_trip_e[i];
        float val = g_trip_v[i];
        float x0 = fmaf(g_x[(size_t)n * 64 + lane],      sc0, sh0);
        float x1 = fmaf(g_x[(size_t)n * 64 + lane + 32], sc1, sh1);
        atomicAdd(&g_pm_x[(size_t)e * 64 + lane],      val * x0);
        atomicAdd(&g_pm_x[(size_t)e * 64 + lane + 32], val * x1);
    }
}

// ---------------- y combine + concat/relu + BN-y stats -> out ----------------
__global__ __launch_bounds__(256) void k_y_linear(const float* __restrict__ gaw,
                                                  const float* __restrict__ gab,
                                                  const float* __restrict__ gxw,
                                                  const float* __restrict__ gxb,
                                                  const float* __restrict__ garw,
                                                  const float* __restrict__ garb,
                                                  const float* __restrict__ gxrw,
                                                  const float* __restrict__ gxrb,
                                                  float* __restrict__ out) {
    __shared__ float s_lg[16 * 64];
    __shared__ float s_pm[16 * 64];
    __shared__ float red[256], red2[256];
    int t = threadIdx.x;
    int rowbase = blockIdx.x * 16;
    reinterpret_cast<float4*>(s_lg)[t] =
        reinterpret_cast<const float4*>(g_lg_y + (size_t)rowbase * 64)[t];
    reinterpret_cast<float4*>(s_pm)[t] =
        reinterpret_cast<const float4*>(g_pm_x + (size_t)rowbase * 64)[t];
    __syncthreads();
    int c = t & 63, slot = t >> 6;
    const float *wa, *wx; float bias; bool dorelu;
    if (c < 32) { wa = gaw + c * 64;   wx = gxw + c * 64;
                  bias = gab[c] + gxb[c];            dorelu = false; }
    else        { int cr = c - 32;
                  wa = garw + cr * 64; wx = gxrw + cr * 64;
                  bias = garb[cr] + gxrb[cr];        dorelu = true;  }
    float acc[4] = {bias, bias, bias, bias};
    #pragma unroll
    for (int f = 0; f < 64; f += 4) {
        float4 wav = *reinterpret_cast<const float4*>(wa + f);
        float4 wxv = *reinterpret_cast<const float4*>(wx + f);
        #pragma unroll
        for (int j = 0; j < 4; ++j) {
            float4 pa = *reinterpret_cast<const float4*>(&s_lg[(slot + 4 * j) * 64 + f]);
            float4 px = *reinterpret_cast<const float4*>(&s_pm[(slot + 4 * j) * 64 + f]);
            float a = acc[j];
            a = fmaf(wav.x, pa.x, fmaf(wav.y, pa.y, fmaf(wav.z, pa.z, fmaf(wav.w, pa.w, a))));
            a = fmaf(wxv.x, px.x, fmaf(wxv.y, px.y, fmaf(wxv.z, px.z, fmaf(wxv.w, px.w, a))));
            acc[j] = a;
        }
    }
    float s = 0.f, sq = 0.f;
    #pragma unroll
    for (int j = 0; j < 4; ++j) {
        float v = acc[j];
        if (dorelu) v = fmaxf(v, 0.f);
        out[(size_t)(rowbase + slot + 4 * j) * 64 + c] = v;
        s += v; sq += v * v;
    }
    red[t] = s; red2[t] = sq;
    __syncthreads();
    if (slot == 0) {
        atomicAdd(&g_stats[128 + c], red[c] + red[64 + c] + red[128 + c] + red[192 + c]);
        atomicAdd(&g_stats[192 + c], red2[c] + red2[64 + c] + red2[128 + c] + red2[192 + c]);
    }
}

// ---------------- final BN on y (vectorized, in place) ----------------
__global__ __launch_bounds__(256) void k_bn_y(float4* __restrict__ buf,
                                              const float* __restrict__ w,
                                              const float* __restrict__ b) {
    int idx = blockIdx.x * 256 + threadIdx.x;
    const float inve = 1.f / EE;
    int c0 = (idx & 15) << 2;
    float4 v = buf[idx];
    float* vp = reinterpret_cast<float*>(&v);
    #pragma unroll
    for (int j = 0; j < 4; ++j) {
        int c = c0 + j;
        float m = g_stats[128 + c] * inve;
        float var = g_stats[192 + c] * inve - m * m;
        float sc = w[c] * rsqrtf(var + BN_EPS);
        vp[j] = (vp[j] - m) * sc + b[c];
    }
    buf[idx] = v;
}

// ---------------- launch ----------------
extern "C" void kernel_launch(void* const* d_in, const int* in_sizes, int n_in,
                              void* d_out, int out_size) {
    const float* y    = (const float*)d_in[0];
    const float* lg   = (const float*)d_in[3];
    const float* pm   = (const float*)d_in[4];
    const float* pd   = (const float*)d_in[5];
    const float* tw   = (const float*)d_in[6];
    const float* tb   = (const float*)d_in[7];
    const float* trw  = (const float*)d_in[8];
    const float* trb  = (const float*)d_in[9];
    const float* gaw  = (const float*)d_in[10];
    const float* gab  = (const float*)d_in[11];
    const float* gxw  = (const float*)d_in[12];
    const float* gxb  = (const float*)d_in[13];
    const float* garw = (const float*)d_in[14];
    const float* garb = (const float*)d_in[15];
    const float* gxrw = (const float*)d_in[16];
    const float* gxrb = (const float*)d_in[17];
    const float* bxw  = (const float*)d_in[18];
    const float* bxb  = (const float*)d_in[19];
    const float* byw  = (const float*)d_in[20];
    const float* byb  = (const float*)d_in[21];
    float* out = (float*)d_out;

    k_init<<<512, 256>>>();
    k_megascan<<<NBLK, 256>>>(pd, lg, pm, y);
    k_x_linear<<<NN / 16, 256>>>(tw, tb, trw, trb);
    k_pm_apply<<<2048, 256>>>(bxw, bxb);
    k_y_linear<<<EE / 16, 256>>>(gaw, gab, gxw, gxb, garw, garb, gxrw, gxrb, out);
    k_bn_y<<<512, 256>>>((float4*)out, byw, byb);
}

// round 6
// speedup vs baseline: 1.0122x; 1.0122x over previous
#include <cuda_runtime.h>
#include <cstdint>

#define NN 4096
#define EE 8192
#define FDIM 64
#define BN_EPS 1e-5f
#define TRIP_CAP 131072
#define TOTROWS (NN + EE + NN)
#define NBLK 740

// ---------------- device scratch ----------------
__device__ float g_pd_y[NN * FDIM];
__device__ float g_x[NN * FDIM];        // raw x (pre-BN)
__device__ float g_lg_y[EE * FDIM];
__device__ float g_pm_x[EE * FDIM];     // pm^T @ x_raw
__device__ float g_cs[EE];              // pm^T @ 1  (col sums per edge)
__device__ float g_stats[256];
__device__ int   g_cnt;
__device__ unsigned g_row_ctr;
__device__ int   g_bar1, g_bar2;
__device__ int   g_trip_n[TRIP_CAP];
__device__ int   g_trip_e[TRIP_CAP];
__device__ float g_trip_v[TRIP_CAP];

// ---------------- tiny init ----------------
__global__ __launch_bounds__(256) void k_init0() {
    int t = threadIdx.x;
    g_stats[t] = 0.f;
    if (t == 0) { g_cnt = 0; g_row_ctr = 0u; g_bar1 = 0; g_bar2 = 0; }
}

// ---------------- helpers ----------------
__device__ __forceinline__ unsigned nz4(float4 v) {
    return __float_as_uint(v.x) | __float_as_uint(v.y) |
           __float_as_uint(v.z) | __float_as_uint(v.w);
}

__device__ __forceinline__ void gath_chunk(float4 v, unsigned ored, int colbase, int lane,
                                           const float* __restrict__ B,
                                           float& acc0, float& acc1) {
    unsigned mask = __ballot_sync(0xffffffffu, ored != 0u);
    while (mask) {
        int src = __ffs(mask) - 1;
        mask &= mask - 1;
        float b0 = __shfl_sync(0xffffffffu, v.x, src);
        float b1 = __shfl_sync(0xffffffffu, v.y, src);
        float b2 = __shfl_sync(0xffffffffu, v.z, src);
        float b3 = __shfl_sync(0xffffffffu, v.w, src);
        const float* bp = B + (size_t)(colbase + (src << 2)) * FDIM + lane;
        if (b0 != 0.f) { acc0 = fmaf(b0, bp[0],   acc0); acc1 = fmaf(b0, bp[32],  acc1); }
        if (b1 != 0.f) { acc0 = fmaf(b1, bp[64],  acc0); acc1 = fmaf(b1, bp[96],  acc1); }
        if (b2 != 0.f) { acc0 = fmaf(b2, bp[128], acc0); acc1 = fmaf(b2, bp[160], acc1); }
        if (b3 != 0.f) { acc0 = fmaf(b3, bp[192], acc0); acc1 = fmaf(b3, bp[224], acc1); }
    }
}

__device__ __forceinline__ void pm_emit(float4 v, int col0, int n) {
    int k = (v.x != 0.f) + (v.y != 0.f) + (v.z != 0.f) + (v.w != 0.f);
    if (!k) return;
    int pos = atomicAdd(&g_cnt, k);
    float vals[4] = {v.x, v.y, v.z, v.w};
    #pragma unroll
    for (int j = 0; j < 4; ++j) {
        if (vals[j] != 0.f && pos < TRIP_CAP) {
            g_trip_n[pos] = n;
            g_trip_e[pos] = col0 + j;
            g_trip_v[pos] = vals[j];
            ++pos;
        }
    }
}

__device__ __forceinline__ void block_barrier(int* bar, int nblocks) {
    __syncthreads();
    __threadfence();
    if (threadIdx.x == 0) {
        atomicAdd(bar, 1);
        while (atomicAdd(bar, 0) < nblocks) { }
    }
    __syncthreads();
    __threadfence();
}

// ---------------- persistent mega-scan (R4, proven) ----------------
__global__ void __launch_bounds__(256, 5) k_megascan(const float* __restrict__ pd,
                                                     const float* __restrict__ lg,
                                                     const float* __restrict__ pm,
                                                     const float* __restrict__ y) {
    int lane = threadIdx.x & 31;
    while (true) {
        unsigned rowid;
        if (lane == 0) rowid = atomicAdd(&g_row_ctr, 1u);
        rowid = __shfl_sync(0xffffffffu, rowid, 0);
        if (rowid >= TOTROWS) return;

        const float4* arow;
        int mode, row;
        if (rowid < NN)            { mode = 0; row = (int)rowid;           arow = reinterpret_cast<const float4*>(pd + (size_t)row * EE); }
        else if (rowid < NN + EE)  { mode = 1; row = (int)rowid - NN;      arow = reinterpret_cast<const float4*>(lg + (size_t)row * EE); }
        else                       { mode = 2; row = (int)rowid - NN - EE; arow = reinterpret_cast<const float4*>(pm + (size_t)row * EE); }

        if (mode < 2) {
            float acc0 = 0.f, acc1 = 0.f;
            #pragma unroll 1
            for (int g = 0; g < EE / 512; ++g) {
                int fb = (g << 7) + lane;
                float4 v0 = __ldcs(arow + fb);
                float4 v1 = __ldcs(arow + fb + 32);
                float4 v2 = __ldcs(arow + fb + 64);
                float4 v3 = __ldcs(arow + fb + 96);
                unsigned o0 = nz4(v0), o1 = nz4(v1), o2 = nz4(v2), o3 = nz4(v3);
                if (__ballot_sync(0xffffffffu, (o0 | o1 | o2 | o3) != 0u)) {
                    int cb = g << 9;
                    gath_chunk(v0, o0, cb,       lane, y, acc0, acc1);
                    gath_chunk(v1, o1, cb + 128, lane, y, acc0, acc1);
                    gath_chunk(v2, o2, cb + 256, lane, y, acc0, acc1);
                    gath_chunk(v3, o3, cb + 384, lane, y, acc0, acc1);
                }
            }
            float* out = (mode == 0 ? g_pd_y : g_lg_y) + (size_t)row * FDIM;
            out[lane]      = acc0;
            out[lane + 32] = acc1;
        } else {
            #pragma unroll 1
            for (int g = 0; g < EE / 512; ++g) {
                int fb = (g << 7) + lane;
                float4 v0 = __ldcs(arow + fb);
                float4 v1 = __ldcs(arow + fb + 32);
                float4 v2 = __ldcs(arow + fb + 64);
                float4 v3 = __ldcs(arow + fb + 96);
                unsigned o0 = nz4(v0), o1 = nz4(v1), o2 = nz4(v2), o3 = nz4(v3);
                if (__ballot_sync(0xffffffffu, (o0 | o1 | o2 | o3) != 0u)) {
                    int cb = (g << 9) + (lane << 2);
                    if (o0) pm_emit(v0, cb,       row);
                    if (o1) pm_emit(v1, cb + 128, row);
                    if (o2) pm_emit(v2, cb + 256, row);
                    if (o3) pm_emit(v3, cb + 384, row);
                }
            }
        }
    }
}

// ---------------- fused: zero pm_x/cs + x_linear + stats + [barrier] + pm scatter (raw x) ----------------
__global__ __launch_bounds__(256) void k_x_pm(const float* __restrict__ tw,
                                              const float* __restrict__ tb,
                                              const float* __restrict__ trw,
                                              const float* __restrict__ trb) {
    __shared__ float s_in[16 * 64];
    __shared__ float red[256], red2[256];
    int t = threadIdx.x;
    int gidx = blockIdx.x * 256 + t;       // 65536 threads

    // zero pm_x (131072 float4) and cs (2048 float4)
    float4 z = make_float4(0.f, 0.f, 0.f, 0.f);
    reinterpret_cast<float4*>(g_pm_x)[gidx]          = z;
    reinterpret_cast<float4*>(g_pm_x)[gidx + 65536]  = z;
    if (gidx < 2048) reinterpret_cast<float4*>(g_cs)[gidx] = z;

    // ---- x linear ----
    int rowbase = blockIdx.x * 16;
    reinterpret_cast<float4*>(s_in)[t] =
        reinterpret_cast<const float4*>(g_pd_y + (size_t)rowbase * 64)[t];
    __syncthreads();
    int c = t & 63, slot = t >> 6;
    const float* w; float bias; bool dorelu;
    if (c < 32) { w = tw + c * 64;         bias = tb[c];        dorelu = false; }
    else        { w = trw + (c - 32) * 64; bias = trb[c - 32];  dorelu = true;  }
    float acc[4] = {bias, bias, bias, bias};
    #pragma unroll
    for (int f = 0; f < 64; f += 4) {
        float4 wv = *reinterpret_cast<const float4*>(w + f);
        #pragma unroll
        for (int j = 0; j < 4; ++j) {
            float4 pv = *reinterpret_cast<const float4*>(&s_in[(slot + 4 * j) * 64 + f]);
            acc[j] = fmaf(wv.x, pv.x, fmaf(wv.y, pv.y, fmaf(wv.z, pv.z, fmaf(wv.w, pv.w, acc[j]))));
        }
    }
    float s = 0.f, sq = 0.f;
    #pragma unroll
    for (int j = 0; j < 4; ++j) {
        float v = acc[j];
        if (dorelu) v = fmaxf(v, 0.f);
        g_x[(size_t)(rowbase + slot + 4 * j) * 64 + c] = v;
        s += v; sq += v * v;
    }
    red[t] = s; red2[t] = sq;
    __syncthreads();
    if (slot == 0) {
        atomicAdd(&g_stats[c],      red[c] + red[64 + c] + red[128 + c] + red[192 + c]);
        atomicAdd(&g_stats[64 + c], red2[c] + red2[64 + c] + red2[128 + c] + red2[192 + c]);
    }

    // ---- barrier: all x rows + zeroing visible ----
    block_barrier(&g_bar1, 256);

    // ---- pm scatter on RAW x, batched 8/warp ----
    int lane = t & 31;
    int warp = blockIdx.x * 8 + (t >> 5);     // 2048 warps
    int cnt = g_cnt; if (cnt > TRIP_CAP) cnt = TRIP_CAP;
    int K = (cnt + 2047) >> 11;
    int base = warp * K;
    int m = cnt - base; if (m > K) m = K;
    for (int j0 = 0; j0 < m; j0 += 8) {
        int mm = m - j0; if (mm > 8) mm = 8;
        int n_[8], e_[8]; float v_[8], x0_[8], x1_[8];
        #pragma unroll
        for (int j = 0; j < 8; ++j) if (j < mm) {
            n_[j] = g_trip_n[base + j0 + j];
            e_[j] = g_trip_e[base + j0 + j];
            v_[j] = g_trip_v[base + j0 + j];
        }
        #pragma unroll
        for (int j = 0; j < 8; ++j) if (j < mm) {
            x0_[j] = g_x[(size_t)n_[j] * 64 + lane];
            x1_[j] = g_x[(size_t)n_[j] * 64 + lane + 32];
        }
        #pragma unroll
        for (int j = 0; j < 8; ++j) if (j < mm) {
            atomicAdd(&g_pm_x[(size_t)e_[j] * 64 + lane],      v_[j] * x0_[j]);
            atomicAdd(&g_pm_x[(size_t)e_[j] * 64 + lane + 32], v_[j] * x1_[j]);
            if (lane == 0) atomicAdd(&g_cs[e_[j]], v_[j]);
        }
    }
}

// ---------------- fused y: combine + relu + stats + [barrier] + BN apply -> out ----------------
__global__ __launch_bounds__(256) void k_y_final(const float* __restrict__ gaw,
                                                 const float* __restrict__ gab,
                                                 const float* __restrict__ gxw,
                                                 const float* __restrict__ gxb,
                                                 const float* __restrict__ garw,
                                                 const float* __restrict__ garb,
                                                 const float* __restrict__ gxrw,
                                                 const float* __restrict__ gxrb,
                                                 const float* __restrict__ bxw,
                                                 const float* __restrict__ bxb,
                                                 const float* __restrict__ byw,
                                                 const float* __restrict__ byb,
                                                 float* __restrict__ out) {
    __shared__ float s_lg[16 * 64];
    __shared__ float s_pm[16 * 64];
    __shared__ float s_cs[16];
    __shared__ float s_sc[64], s_sh[64];
    __shared__ float red[256], red2[256];
    int t = threadIdx.x;
    int rowbase = blockIdx.x * 16;

    // x-BN affine per channel (from stats)
    if (t < 64) {
        const float invn = 1.f / NN;
        float m = g_stats[t] * invn;
        float var = g_stats[64 + t] * invn - m * m;
        float sc = bxw[t] * rsqrtf(var + BN_EPS);
        s_sc[t] = sc;
        s_sh[t] = bxb[t] - m * sc;
    }
    if (t < 16) s_cs[t] = g_cs[rowbase + t];
    reinterpret_cast<float4*>(s_lg)[t] =
        reinterpret_cast<const float4*>(g_lg_y + (size_t)rowbase * 64)[t];
    reinterpret_cast<float4*>(s_pm)[t] =
        reinterpret_cast<const float4*>(g_pm_x + (size_t)rowbase * 64)[t];
    __syncthreads();

    int c = t & 63, slot = t >> 6;
    const float *wa, *wx; float bias; bool dorelu;
    if (c < 32) { wa = gaw + c * 64;   wx = gxw + c * 64;
                  bias = gab[c] + gxb[c];            dorelu = false; }
    else        { int cr = c - 32;
                  wa = garw + cr * 64; wx = gxrw + cr * 64;
                  bias = garb[cr] + gxrb[cr];        dorelu = true;  }
    float acc[4] = {bias, bias, bias, bias};
    float wsh = 0.f;
    #pragma unroll
    for (int f = 0; f < 64; f += 4) {
        float4 wav = *reinterpret_cast<const float4*>(wa + f);
        float4 wxv = *reinterpret_cast<const float4*>(wx + f);
        float4 scv = *reinterpret_cast<const float4*>(&s_sc[f]);
        float4 shv = *reinterpret_cast<const float4*>(&s_sh[f]);
        wsh = fmaf(wxv.x, shv.x, fmaf(wxv.y, shv.y, fmaf(wxv.z, shv.z, fmaf(wxv.w, shv.w, wsh))));
        wxv.x *= scv.x; wxv.y *= scv.y; wxv.z *= scv.z; wxv.w *= scv.w;
        #pragma unroll
        for (int j = 0; j < 4; ++j) {
            float4 pa = *reinterpret_cast<const float4*>(&s_lg[(slot + 4 * j) * 64 + f]);
            float4 px = *reinterpret_cast<const float4*>(&s_pm[(slot + 4 * j) * 64 + f]);
            float a = acc[j];
            a = fmaf(wav.x, pa.x, fmaf(wav.y, pa.y, fmaf(wav.z, pa.z, fmaf(wav.w, pa.w, a))));
            a = fmaf(wxv.x, px.x, fmaf(wxv.y, px.y, fmaf(wxv.z, px.z, fmaf(wxv.w, px.w, a))));
            acc[j] = a;
        }
    }
    float s = 0.f, sq = 0.f;
    #pragma unroll
    for (int j = 0; j < 4; ++j) {
        float v = acc[j] + s_cs[slot + 4 * j] * wsh;
        if (dorelu) v = fmaxf(v, 0.f);
        acc[j] = v;
        s += v; sq += v * v;
    }
    red[t] = s; red2[t] = sq;
    __syncthreads();
    if (slot == 0) {
        atomicAdd(&g_stats[128 + c], red[c] + red[64 + c] + red[128 + c] + red[192 + c]);
        atomicAdd(&g_stats[192 + c], red2[c] + red2[64 + c] + red2[128 + c] + red2[192 + c]);
    }

    block_barrier(&g_bar2, 512);

    const float inve = 1.f / EE;
    float m = g_stats[128 + c] * inve;
    float var = g_stats[192 + c] * inve - m * m;
    float scy = byw[c] * rsqrtf(var + BN_EPS);
    float shy = byb[c] - m * scy;
    #pragma unroll
    for (int j = 0; j < 4; ++j)
        out[(size_t)(rowbase + slot + 4 * j) * 64 + c] = fmaf(acc[j], scy, shy);
}

// ---------------- launch ----------------
extern "C" void kernel_launch(void* const* d_in, const int* in_sizes, int n_in,
                              void* d_out, int out_size) {
    const float* y    = (const float*)d_in[0];
    const float* lg   = (const float*)d_in[3];
    const float* pm   = (const float*)d_in[4];
    const float* pd   = (const float*)d_in[5];
    const float* tw   = (const float*)d_in[6];
    const float* tb   = (const float*)d_in[7];
    const float* trw  = (const float*)d_in[8];
    const float* trb  = (const float*)d_in[9];
    const float* gaw  = (const float*)d_in[10];
    const float* gab  = (const float*)d_in[11];
    const float* gxw  = (const float*)d_in[12];
    const float* gxb  = (const float*)d_in[13];
    const float* garw = (const float*)d_in[14];
    const float* garb = (const float*)d_in[15];
    const float* gxrw = (const float*)d_in[16];
    const float* gxrb = (const float*)d_in[17];
    const float* bxw  = (const float*)d_in[18];
    const float* bxb  = (const float*)d_in[19];
    const float* byw  = (const float*)d_in[20];
    const float* byb  = (const float*)d_in[21];
    float* out = (float*)d_out;

    k_init0<<<1, 256>>>();
    k_megascan<<<NBLK, 256>>>(pd, lg, pm, y);
    k_x_pm<<<256, 256>>>(tw, tb, trw, trb);
    k_y_final<<<512, 256>>>(gaw, gab, gxw, gxb, garw, garb, gxrw, gxrb,
                            bxw, bxb, byw, byb, out);
}

// round 7
// speedup vs baseline: 1.0460x; 1.0334x over previous
#include <cuda_runtime.h>
#include <cstdint>

#define NN 4096
#define EE 8192
#define FDIM 64
#define BN_EPS 1e-5f
#define TRIP_CAP 131072
#define TOTROWS (NN + EE + NN)
#define NBLK 740

// ---------------- device scratch ----------------
__device__ float g_pd_y[NN * FDIM];
__device__ float g_x[NN * FDIM];
__device__ float g_lg_y[EE * FDIM];
__device__ float g_pm_x[EE * FDIM];
__device__ float g_stats[256];
__device__ int   g_cnt;
__device__ unsigned g_row_ctr;
__device__ int   g_trip_n[TRIP_CAP];
__device__ int   g_trip_e[TRIP_CAP];
__device__ float g_trip_v[TRIP_CAP];

// ---------------- init ----------------
__global__ __launch_bounds__(256) void k_init() {
    int idx = blockIdx.x * 256 + threadIdx.x;              // 512*256 = 131072
    reinterpret_cast<float4*>(g_pm_x)[idx] = make_float4(0.f, 0.f, 0.f, 0.f);
    if (idx < 256) g_stats[idx] = 0.f;
    if (idx == 0) { g_cnt = 0; g_row_ctr = 0u; }
}

// ---------------- helpers ----------------
__device__ __forceinline__ unsigned nz4(float4 v) {
    return __float_as_uint(v.x) | __float_as_uint(v.y) |
           __float_as_uint(v.z) | __float_as_uint(v.w);
}

__device__ __forceinline__ void gath_chunk(float4 v, unsigned ored, int colbase, int lane,
                                           const float* __restrict__ B,
                                           float& acc0, float& acc1) {
    unsigned mask = __ballot_sync(0xffffffffu, ored != 0u);
    while (mask) {
        int src = __ffs(mask) - 1;
        mask &= mask - 1;
        float b0 = __shfl_sync(0xffffffffu, v.x, src);
        float b1 = __shfl_sync(0xffffffffu, v.y, src);
        float b2 = __shfl_sync(0xffffffffu, v.z, src);
        float b3 = __shfl_sync(0xffffffffu, v.w, src);
        const float* bp = B + (size_t)(colbase + (src << 2)) * FDIM + lane;
        if (b0 != 0.f) { acc0 = fmaf(b0, bp[0],   acc0); acc1 = fmaf(b0, bp[32],  acc1); }
        if (b1 != 0.f) { acc0 = fmaf(b1, bp[64],  acc0); acc1 = fmaf(b1, bp[96],  acc1); }
        if (b2 != 0.f) { acc0 = fmaf(b2, bp[128], acc0); acc1 = fmaf(b2, bp[160], acc1); }
        if (b3 != 0.f) { acc0 = fmaf(b3, bp[192], acc0); acc1 = fmaf(b3, bp[224], acc1); }
    }
}

__device__ __forceinline__ void pm_emit(float4 v, int col0, int n) {
    int k = (v.x != 0.f) + (v.y != 0.f) + (v.z != 0.f) + (v.w != 0.f);
    if (!k) return;
    int pos = atomicAdd(&g_cnt, k);
    float vals[4] = {v.x, v.y, v.z, v.w};
    #pragma unroll
    for (int j = 0; j < 4; ++j) {
        if (vals[j] != 0.f && pos < TRIP_CAP) {
            g_trip_n[pos] = n;
            g_trip_e[pos] = col0 + j;
            g_trip_v[pos] = vals[j];
            ++pos;
        }
    }
}

// ---------------- persistent mega-scan (R4, proven) ----------------
__global__ void __launch_bounds__(256, 5) k_megascan(const float* __restrict__ pd,
                                                     const float* __restrict__ lg,
                                                     const float* __restrict__ pm,
                                                     const float* __restrict__ y) {
    int lane = threadIdx.x & 31;
    while (true) {
        unsigned rowid;
        if (lane == 0) rowid = atomicAdd(&g_row_ctr, 1u);
        rowid = __shfl_sync(0xffffffffu, rowid, 0);
        if (rowid >= TOTROWS) return;

        const float4* arow;
        int mode, row;
        if (rowid < NN)            { mode = 0; row = (int)rowid;           arow = reinterpret_cast<const float4*>(pd + (size_t)row * EE); }
        else if (rowid < NN + EE)  { mode = 1; row = (int)rowid - NN;      arow = reinterpret_cast<const float4*>(lg + (size_t)row * EE); }
        else                       { mode = 2; row = (int)rowid - NN - EE; arow = reinterpret_cast<const float4*>(pm + (size_t)row * EE); }

        if (mode < 2) {
            float acc0 = 0.f, acc1 = 0.f;
            #pragma unroll 1
            for (int g = 0; g < EE / 512; ++g) {
                int fb = (g << 7) + lane;
                float4 v0 = __ldcs(arow + fb);
                float4 v1 = __ldcs(arow + fb + 32);
                float4 v2 = __ldcs(arow + fb + 64);
                float4 v3 = __ldcs(arow + fb + 96);
                unsigned o0 = nz4(v0), o1 = nz4(v1), o2 = nz4(v2), o3 = nz4(v3);
                if (__ballot_sync(0xffffffffu, (o0 | o1 | o2 | o3) != 0u)) {
                    int cb = g << 9;
                    gath_chunk(v0, o0, cb,       lane, y, acc0, acc1);
                    gath_chunk(v1, o1, cb + 128, lane, y, acc0, acc1);
                    gath_chunk(v2, o2, cb + 256, lane, y, acc0, acc1);
                    gath_chunk(v3, o3, cb + 384, lane, y, acc0, acc1);
                }
            }
            float* out = (mode == 0 ? g_pd_y : g_lg_y) + (size_t)row * FDIM;
            out[lane]      = acc0;
            out[lane + 32] = acc1;
        } else {
            #pragma unroll 1
            for (int g = 0; g < EE / 512; ++g) {
                int fb = (g << 7) + lane;
                float4 v0 = __ldcs(arow + fb);
                float4 v1 = __ldcs(arow + fb + 32);
                float4 v2 = __ldcs(arow + fb + 64);
                float4 v3 = __ldcs(arow + fb + 96);
                unsigned o0 = nz4(v0), o1 = nz4(v1), o2 = nz4(v2), o3 = nz4(v3);
                if (__ballot_sync(0xffffffffu, (o0 | o1 | o2 | o3) != 0u)) {
                    int cb = (g << 9) + (lane << 2);
                    if (o0) pm_emit(v0, cb,       row);
                    if (o1) pm_emit(v1, cb + 128, row);
                    if (o2) pm_emit(v2, cb + 256, row);
                    if (o3) pm_emit(v3, cb + 384, row);
                }
            }
        }
    }
}

// ---------------- x linear + concat/relu + BN-x stats ----------------
__global__ __launch_bounds__(256) void k_x_linear(const float* __restrict__ tw,
                                                  const float* __restrict__ tb,
                                                  const float* __restrict__ trw,
                                                  const float* __restrict__ trb) {
    __shared__ float s_in[16 * 64];
    __shared__ float red[256], red2[256];
    int t = threadIdx.x;
    int rowbase = blockIdx.x * 16;
    reinterpret_cast<float4*>(s_in)[t] =
        reinterpret_cast<const float4*>(g_pd_y + (size_t)rowbase * 64)[t];
    __syncthreads();
    int c = t & 63, slot = t >> 6;
    const float* w; float bias; bool dorelu;
    if (c < 32) { w = tw + c * 64;         bias = tb[c];        dorelu = false; }
    else        { w = trw + (c - 32) * 64; bias = trb[c - 32];  dorelu = true;  }
    float acc[4] = {bias, bias, bias, bias};
    #pragma unroll
    for (int f = 0; f < 64; f += 4) {
        float4 wv = *reinterpret_cast<const float4*>(w + f);
        #pragma unroll
        for (int j = 0; j < 4; ++j) {
            float4 pv = *reinterpret_cast<const float4*>(&s_in[(slot + 4 * j) * 64 + f]);
            acc[j] = fmaf(wv.x, pv.x, fmaf(wv.y, pv.y, fmaf(wv.z, pv.z, fmaf(wv.w, pv.w, acc[j]))));
        }
    }
    float s = 0.f, sq = 0.f;
    #pragma unroll
    for (int j = 0; j < 4; ++j) {
        float v = acc[j];
        if (dorelu) v = fmaxf(v, 0.f);
        g_x[(size_t)(rowbase + slot + 4 * j) * 64 + c] = v;
        s += v; sq += v * v;
    }
    red[t] = s; red2[t] = sq;
    __syncthreads();
    if (slot == 0) {
        atomicAdd(&g_stats[c],      red[c] + red[64 + c] + red[128 + c] + red[192 + c]);
        atomicAdd(&g_stats[64 + c], red2[c] + red2[64 + c] + red2[128 + c] + red2[192 + c]);
    }
}

// ---------------- pm triplet apply, fused x-BN, batched per warp ----------------
__global__ __launch_bounds__(256) void k_pm_apply(const float* __restrict__ bxw,
                                                  const float* __restrict__ bxb) {
    int lane = threadIdx.x & 31;
    int warp = (blockIdx.x * 256 + threadIdx.x) >> 5;   // 4096 warps

    int cnt = g_cnt;
    if (cnt > TRIP_CAP) cnt = TRIP_CAP;
    int K = (cnt + 4095) >> 12;                          // triplets per warp
    int base = warp * K;
    int m = cnt - base; if (m < 0) m = 0; if (m > K) m = K;
    if (m == 0) return;

    const float invn = 1.f / NN;
    float m0 = g_stats[lane] * invn;
    float m1 = g_stats[lane + 32] * invn;
    float v0 = g_stats[64 + lane] * invn - m0 * m0;
    float v1 = g_stats[64 + lane + 32] * invn - m1 * m1;
    float sc0 = bxw[lane] * rsqrtf(v0 + BN_EPS);
    float sc1 = bxw[lane + 32] * rsqrtf(v1 + BN_EPS);
    float sh0 = bxb[lane] - m0 * sc0;
    float sh1 = bxb[lane + 32] - m1 * sc1;

    for (int j0 = 0; j0 < m; j0 += 8) {
        int mm = m - j0; if (mm > 8) mm = 8;
        int n_[8], e_[8]; float v_[8], x0_[8], x1_[8];
        #pragma unroll
        for (int j = 0; j < 8; ++j) if (j < mm) {
            n_[j] = g_trip_n[base + j0 + j];
            e_[j] = g_trip_e[base + j0 + j];
            v_[j] = g_trip_v[base + j0 + j];
        }
        #pragma unroll
        for (int j = 0; j < 8; ++j) if (j < mm) {
            x0_[j] = g_x[(size_t)n_[j] * 64 + lane];
            x1_[j] = g_x[(size_t)n_[j] * 64 + lane + 32];
        }
        #pragma unroll
        for (int j = 0; j < 8; ++j) if (j < mm) {
            float a0 = v_[j] * fmaf(x0_[j], sc0, sh0);
            float a1 = v_[j] * fmaf(x1_[j], sc1, sh1);
            atomicAdd(&g_pm_x[(size_t)e_[j] * 64 + lane],      a0);
            atomicAdd(&g_pm_x[(size_t)e_[j] * 64 + lane + 32], a1);
        }
    }
}

// ---------------- y combine + concat/relu + BN-y stats -> out ----------------
__global__ __launch_bounds__(256) void k_y_linear(const float* __restrict__ gaw,
                                                  const float* __restrict__ gab,
                                                  const float* __restrict__ gxw,
                                                  const float* __restrict__ gxb,
                                                  const float* __restrict__ garw,
                                                  const float* __restrict__ garb,
                                                  const float* __restrict__ gxrw,
                                                  const float* __restrict__ gxrb,
                                                  float* __restrict__ out) {
    __shared__ float s_lg[16 * 64];
    __shared__ float s_pm[16 * 64];
    __shared__ float red[256], red2[256];
    int t = threadIdx.x;
    int rowbase = blockIdx.x * 16;
    reinterpret_cast<float4*>(s_lg)[t] =
        reinterpret_cast<const float4*>(g_lg_y + (size_t)rowbase * 64)[t];
    reinterpret_cast<float4*>(s_pm)[t] =
        reinterpret_cast<const float4*>(g_pm_x + (size_t)rowbase * 64)[t];
    __syncthreads();
    int c = t & 63, slot = t >> 6;
    const float *wa, *wx; float bias; bool dorelu;
    if (c < 32) { wa = gaw + c * 64;   wx = gxw + c * 64;
                  bias = gab[c] + gxb[c];            dorelu = false; }
    else        { int cr = c - 32;
                  wa = garw + cr * 64; wx = gxrw + cr * 64;
                  bias = garb[cr] + gxrb[cr];        dorelu = true;  }
    float acc[4] = {bias, bias, bias, bias};
    #pragma unroll
    for (int f = 0; f < 64; f += 4) {
        float4 wav = *reinterpret_cast<const float4*>(wa + f);
        float4 wxv = *reinterpret_cast<const float4*>(wx + f);
        #pragma unroll
        for (int j = 0; j < 4; ++j) {
            float4 pa = *reinterpret_cast<const float4*>(&s_lg[(slot + 4 * j) * 64 + f]);
            float4 px = *reinterpret_cast<const float4*>(&s_pm[(slot + 4 * j) * 64 + f]);
            float a = acc[j];
            a = fmaf(wav.x, pa.x, fmaf(wav.y, pa.y, fmaf(wav.z, pa.z, fmaf(wav.w, pa.w, a))));
            a = fmaf(wxv.x, px.x, fmaf(wxv.y, px.y, fmaf(wxv.z, px.z, fmaf(wxv.w, px.w, a))));
            acc[j] = a;
        }
    }
    float s = 0.f, sq = 0.f;
    #pragma unroll
    for (int j = 0; j < 4; ++j) {
        float v = acc[j];
        if (dorelu) v = fmaxf(v, 0.f);
        out[(size_t)(rowbase + slot + 4 * j) * 64 + c] = v;
        s += v; sq += v * v;
    }
    red[t] = s; red2[t] = sq;
    __syncthreads();
    if (slot == 0) {
        atomicAdd(&g_stats[128 + c], red[c] + red[64 + c] + red[128 + c] + red[192 + c]);
        atomicAdd(&g_stats[192 + c], red2[c] + red2[64 + c] + red2[128 + c] + red2[192 + c]);
    }
}

// ---------------- final BN on y (vectorized, in place) ----------------
__global__ __launch_bounds__(256) void k_bn_y(float4* __restrict__ buf,
                                              const float* __restrict__ w,
                                              const float* __restrict__ b) {
    int idx = blockIdx.x * 256 + threadIdx.x;
    const float inve = 1.f / EE;
    int c0 = (idx & 15) << 2;
    float4 v = buf[idx];
    float* vp = reinterpret_cast<float*>(&v);
    #pragma unroll
    for (int j = 0; j < 4; ++j) {
        int c = c0 + j;
        float m = g_stats[128 + c] * inve;
        float var = g_stats[192 + c] * inve - m * m;
        float sc = w[c] * rsqrtf(var + BN_EPS);
        vp[j] = (vp[j] - m) * sc + b[c];
    }
    buf[idx] = v;
}

// ---------------- launch ----------------
extern "C" void kernel_launch(void* const* d_in, const int* in_sizes, int n_in,
                              void* d_out, int out_size) {
    const float* y    = (const float*)d_in[0];
    const float* lg   = (const float*)d_in[3];
    const float* pm   = (const float*)d_in[4];
    const float* pd   = (const float*)d_in[5];
    const float* tw   = (const float*)d_in[6];
    const float* tb   = (const float*)d_in[7];
    const float* trw  = (const float*)d_in[8];
    const float* trb  = (const float*)d_in[9];
    const float* gaw  = (const float*)d_in[10];
    const float* gab  = (const float*)d_in[11];
    const float* gxw  = (const float*)d_in[12];
    const float* gxb  = (const float*)d_in[13];
    const float* garw = (const float*)d_in[14];
    const float* garb = (const float*)d_in[15];
    const float* gxrw = (const float*)d_in[16];
    const float* gxrb = (const float*)d_in[17];
    const float* bxw  = (const float*)d_in[18];
    const float* bxb  = (const float*)d_in[19];
    const float* byw  = (const float*)d_in[20];
    const float* byb  = (const float*)d_in[21];
    float* out = (float*)d_out;

    k_init<<<512, 256>>>();
    k_megascan<<<NBLK, 256>>>(pd, lg, pm, y);
    k_x_linear<<<NN / 16, 256>>>(tw, tb, trw, trb);
    k_pm_apply<<<512, 256>>>(bxw, bxb);
    k_y_linear<<<EE / 16, 256>>>(gaw, gab, gxw, gxb, garw, garb, gxrw, gxrb, out);
    k_bn_y<<<512, 256>>>((float4*)out, byw, byb);
}